// round 10
// baseline (speedup 1.0000x reference)
#include <cuda_runtime.h>
#include <cuda_fp16.h>
#include <math.h>
#include <stdint.h>

#define BT      8192
#define D_DIM   1024
#define E_NUM   8
#define H_DIM   4096
#define CAP     (2*BT)
#define NSLOT   (2*BT)

// ---------------- device scratch ----------------
__device__ __half g_x[(size_t)BT * D_DIM];
__device__ __half g_w1t[(size_t)E_NUM * H_DIM * D_DIM];
__device__ __half g_w2t[(size_t)E_NUM * D_DIM * H_DIM];
__device__ __half g_h[(size_t)NSLOT * H_DIM];
__device__ int   g_slots[E_NUM * CAP];
__device__ float g_gp[NSLOT];
__device__ int   g_cnt[E_NUM];
__device__ float g_imp[E_NUM];
__device__ int   g_loadc[E_NUM];

// ---------------- PTX helpers ----------------
__device__ __forceinline__ uint32_t smem_u32(const void* p) {
    return (uint32_t)__cvta_generic_to_shared(p);
}
__device__ __forceinline__ void cp_async16(uint32_t dst, const void* src) {
    asm volatile("cp.async.cg.shared.global [%0], [%1], 16;" :: "r"(dst), "l"(src));
}
#define CP_COMMIT() asm volatile("cp.async.commit_group;" ::: "memory")
#define CP_WAIT1()  asm volatile("cp.async.wait_group 1;" ::: "memory")

__device__ __forceinline__ void ldmatrix_x4(uint32_t* r, uint32_t addr) {
    asm volatile("ldmatrix.sync.aligned.m8n8.x4.shared.b16 {%0,%1,%2,%3}, [%4];"
        : "=r"(r[0]), "=r"(r[1]), "=r"(r[2]), "=r"(r[3]) : "r"(addr));
}
__device__ __forceinline__ void mma_16816(float* d, const uint32_t* a,
                                          uint32_t b0, uint32_t b1) {
    asm volatile(
        "mma.sync.aligned.m16n8k16.row.col.f32.f16.f16.f32 "
        "{%0,%1,%2,%3}, {%4,%5,%6,%7}, {%8,%9}, {%0,%1,%2,%3};"
        : "+f"(d[0]), "+f"(d[1]), "+f"(d[2]), "+f"(d[3])
        : "r"(a[0]), "r"(a[1]), "r"(a[2]), "r"(a[3]), "r"(b0), "r"(b1));
}
__device__ __forceinline__ void red_add_f32(float* addr, float v) {
    asm volatile("red.global.add.f32 [%0], %1;" :: "l"(addr), "f"(v) : "memory");
}

// ---------------- init ----------------
__global__ void init_kernel() {
    int i = threadIdx.x;
    if (i < E_NUM) { g_cnt[i] = 0; g_imp[i] = 0.f; g_loadc[i] = 0; }
}

// ---------------- zero y ----------------
__global__ void __launch_bounds__(256) zero_y_kernel(float* __restrict__ y) {
    size_t i = (size_t)blockIdx.x * 256 + threadIdx.x;
    ((float4*)y)[i] = make_float4(0.f, 0.f, 0.f, 0.f);
}

// ---------------- router (+ fused x->fp16 conversion) ----------------
__global__ void __launch_bounds__(256) router_kernel(const float* __restrict__ x,
                                                     const float* __restrict__ gW) {
    __shared__ float sW[E_NUM][D_DIM];
    __shared__ float s_imp[E_NUM];
    __shared__ int   s_load[E_NUM];
    int tid = threadIdx.x;
    if (tid < E_NUM) { s_imp[tid] = 0.f; s_load[tid] = 0; }
    for (int i = tid; i < D_DIM * E_NUM; i += 256) {
        int d = i / E_NUM, e = i % E_NUM;
        sW[e][d] = gW[i];
    }
    __syncthreads();

    int warp = tid >> 5, lane = tid & 31;
    int t = blockIdx.x * 8 + warp;
    const float* xr = x + (size_t)t * D_DIM;

    float acc[E_NUM];
#pragma unroll
    for (int e = 0; e < E_NUM; e++) acc[e] = 0.f;
    for (int d4 = lane; d4 < D_DIM / 4; d4 += 32) {
        float4 v = ((const float4*)xr)[d4];
        float f[4] = {v.x, v.y, v.z, v.w};
        __half h[4];
#pragma unroll
        for (int q = 0; q < 4; q++) {
            h[q] = __float2half_rn(f[q]);
#pragma unroll
            for (int e = 0; e < E_NUM; e++)
                acc[e] = fmaf(f[q], sW[e][d4 * 4 + q], acc[e]);
        }
        ((uint2*)g_x)[(size_t)t * (D_DIM / 4) + d4] = *(uint2*)&h[0];
    }
#pragma unroll
    for (int off = 16; off > 0; off >>= 1) {
#pragma unroll
        for (int e = 0; e < E_NUM; e++)
            acc[e] += __shfl_xor_sync(0xffffffffu, acc[e], off);
    }

    if (lane == 0) {
        float mx = acc[0];
#pragma unroll
        for (int e = 1; e < E_NUM; e++) mx = fmaxf(mx, acc[e]);
        float p[E_NUM], s = 0.f;
#pragma unroll
        for (int e = 0; e < E_NUM; e++) { p[e] = expf(acc[e] - mx); s += p[e]; }
        float inv = 1.f / s;
#pragma unroll
        for (int e = 0; e < E_NUM; e++) p[e] *= inv;

        int e1 = 0; float v1 = p[0];
#pragma unroll
        for (int e = 1; e < E_NUM; e++) if (p[e] > v1) { v1 = p[e]; e1 = e; }
        int e2 = -1; float v2 = -1.f;
#pragma unroll
        for (int e = 0; e < E_NUM; e++) if (e != e1 && p[e] > v2) { v2 = p[e]; e2 = e; }

        float ginv = 1.f / (v1 + v2);
        g_gp[2 * t]     = v1 * ginv;
        g_gp[2 * t + 1] = v2 * ginv;

        int p1 = atomicAdd(&g_cnt[e1], 1); g_slots[e1 * CAP + p1] = 2 * t;
        int p2 = atomicAdd(&g_cnt[e2], 1); g_slots[e2 * CAP + p2] = 2 * t + 1;
#pragma unroll
        for (int e = 0; e < E_NUM; e++) atomicAdd(&s_imp[e], p[e]);
        atomicAdd(&s_load[e1], 1);
    }
    __syncthreads();
    if (tid < E_NUM) {
        atomicAdd(&g_imp[tid], s_imp[tid]);
        atomicAdd(&g_loadc[tid], s_load[tid]);
    }
}

// ---------------- convert + transpose weights (single fp16) ----------------
template <int K, int N, bool IS_W1>
__global__ void __launch_bounds__(256) convert_w_kernel(const float* __restrict__ W) {
    __shared__ float tile[32][33];
    int e  = blockIdx.z;
    int n0 = blockIdx.x * 32;
    int k0 = blockIdx.y * 32;
    int t  = threadIdx.x;
    const float* Wb = W + (size_t)e * K * N;
#pragma unroll
    for (int j = 0; j < 4; j++) {
        int i = t + 256 * j;
        int k = i >> 5, n = i & 31;
        tile[k][n] = Wb[(size_t)(k0 + k) * N + n0 + n];
    }
    __syncthreads();
    __half* th = (IS_W1 ? g_w1t : g_w2t) + (size_t)e * N * K;
    int nn = t >> 3;
    int kc = (t & 7) * 4;
    __half h[4];
#pragma unroll
    for (int q = 0; q < 4; q++) h[q] = __float2half_rn(tile[kc + q][nn]);
    size_t o = (size_t)(n0 + nn) * K + k0 + kc;
    *(uint2*)&th[o] = *(uint2*)&h[0];
}

// ---------------- mma.sync grouped GEMM ----------------
// CTA tile 128x256, 512 threads (16 warps, 4m x 4n; warp tile 32x64).
// K-chunk 64, 3-stage cp.async (144KB). Single sync per chunk.
// PHASE2 fuses gate-weighted reduce into y via red.global.
template <int N_TOT, int K_SIZE, bool PHASE1>
__global__ void __launch_bounds__(512, 1) gemm_tc(const float* __restrict__ bias,
                                                  float* __restrict__ yout) {
    int e   = blockIdx.z;
    int cnt = g_cnt[e];
    int m0  = blockIdx.y * 128;
    if (m0 >= cnt) return;
    int n0  = blockIdx.x * 256;

    extern __shared__ char smem[];
    uint32_t sb = smem_u32(smem);
    const int STAGE = 49152;            // 16KB A + 32KB B
    const int AOF = 0, BOF = 16384;

    __shared__ int   sSlot[128];
    __shared__ float sBias[256];
    __shared__ float sGp[128];

    int tid  = threadIdx.x;
    int lane = tid & 31;
    int w    = tid >> 5;       // 0..15
    int wm   = w >> 2;         // 0..3, 32-row slab
    int wn   = w & 3;          // 0..3, 64-col slab

    if (tid < 128) {
        int m = m0 + tid;
        int s = (m < cnt) ? g_slots[e * CAP + m] : -1;
        sSlot[tid] = s;
        if (!PHASE1) sGp[tid] = (s >= 0) ? g_gp[s] : 0.f;
    }
    if (tid < 256) sBias[tid] = bias[(size_t)e * N_TOT + n0 + tid];
    __syncthreads();

    // zero A areas of all stages if ragged m-tile
    if (cnt - m0 < 128) {
#pragma unroll
        for (int s = 0; s < 3; s++) {
            uint32_t base = sb + s * STAGE + AOF;
            for (int off = tid * 16; off < 16384; off += 512 * 16)
                asm volatile("st.shared.v4.b32 [%0], {%1,%1,%1,%1};" :: "r"(base + off), "r"(0) : "memory");
        }
        __syncthreads();
    }

    const __half* Ap = PHASE1 ? g_x   : g_h;
    const __half* Bp = PHASE1 ? g_w1t : g_w2t;

    // loaders: 8 threads per 128B row; A rows 0..127 (2 passes), B rows 0..255 (4 passes)
    const char* aP[2];
    const char* bP[4];
    bool aval[2];
    uint32_t dswA[2], dswB[4];
    int colB = (tid & 7) * 16;
#pragma unroll
    for (int j = 0; j < 2; j++) {
        int row = (tid >> 3) + j * 64;
        int s   = sSlot[row];
        aval[j] = (s >= 0);
        size_t arow = 0;
        if (aval[j]) arow = PHASE1 ? (size_t)(s >> 1) : (size_t)s;
        aP[j] = (const char*)(Ap + arow * K_SIZE) + colB;
        uint32_t off = (uint32_t)row * 128 + colB;
        dswA[j] = off ^ ((off >> 3) & 0x70);
    }
#pragma unroll
    for (int j = 0; j < 4; j++) {
        int row = (tid >> 3) + j * 64;      // 0..255
        size_t nrow = (size_t)e * N_TOT + n0 + row;
        bP[j] = (const char*)(Bp + nrow * K_SIZE) + colB;
        uint32_t off = (uint32_t)row * 128 + colB;
        dswB[j] = off ^ ((off >> 3) & 0x70);
    }

#define LOAD_CHUNK(c) do { \
        uint32_t base_ = sb + ((c) % 3) * STAGE; \
        size_t kb_ = (size_t)(c) * 128; \
        _Pragma("unroll") \
        for (int j = 0; j < 2; j++) \
            if (aval[j]) cp_async16(base_ + AOF + dswA[j], aP[j] + kb_); \
        _Pragma("unroll") \
        for (int j = 0; j < 4; j++) \
            cp_async16(base_ + BOF + dswB[j], bP[j] + kb_); \
    } while (0)

    int lrow = ((lane >> 3) & 1) * 8 + (lane & 7);
    int lkb  = (lane >> 4) * 16;

    float acc[2][8][4];
#pragma unroll
    for (int i = 0; i < 2; i++)
#pragma unroll
        for (int j = 0; j < 8; j++)
#pragma unroll
            for (int q = 0; q < 4; q++) acc[i][j][q] = 0.f;

    constexpr int C = K_SIZE / 64;
    LOAD_CHUNK(0); CP_COMMIT();
    LOAD_CHUNK(1); CP_COMMIT();

    for (int c = 0; c < C; c++) {
        uint32_t base = sb + (c % 3) * STAGE;
        CP_WAIT1();
        __syncthreads();
        // prefetch chunk c+2 into stage (c-1)%3 — drained, proven by barrier above
        if (c + 2 < C) LOAD_CHUNK(c + 2);
        CP_COMMIT();

#pragma unroll
        for (int kk = 0; kk < 4; kk++) {
            int kb = kk * 32 + lkb;
            uint32_t ah[2][4];
#pragma unroll
            for (int mi = 0; mi < 2; mi++) {
                uint32_t off = (uint32_t)(wm * 32 + mi * 16 + lrow) * 128 + kb;
                uint32_t sw  = off ^ ((off >> 3) & 0x70);
                ldmatrix_x4(ah[mi], base + AOF + sw);
            }
            uint32_t bh[4][4];
#pragma unroll
            for (int ng = 0; ng < 4; ng++) {
                uint32_t off = (uint32_t)(wn * 64 + ng * 16 + lrow) * 128 + kb;
                uint32_t sw  = off ^ ((off >> 3) & 0x70);
                ldmatrix_x4(bh[ng], base + BOF + sw);
            }
#pragma unroll
            for (int mi = 0; mi < 2; mi++) {
#pragma unroll
                for (int ng = 0; ng < 4; ng++) {
#pragma unroll
                    for (int jj = 0; jj < 2; jj++) {
                        int nj = ng * 2 + jj;
                        mma_16816(acc[mi][nj], ah[mi], bh[ng][jj], bh[ng][jj + 2]);
                    }
                }
            }
        }
    }
#undef LOAD_CHUNK

    // ---------------- epilogue ----------------
#pragma unroll
    for (int mi = 0; mi < 2; mi++) {
#pragma unroll
        for (int h2 = 0; h2 < 2; h2++) {
            int rloc = wm * 32 + mi * 16 + h2 * 8 + (lane >> 2);
            int slot = sSlot[rloc];
            if (slot < 0) continue;
            float gp = PHASE1 ? 0.f : sGp[rloc];
#pragma unroll
            for (int nj = 0; nj < 8; nj++) {
                int cl = wn * 64 + nj * 8 + (lane & 3) * 2;
                float v0 = acc[mi][nj][h2 * 2 + 0] + sBias[cl];
                float v1 = acc[mi][nj][h2 * 2 + 1] + sBias[cl + 1];
                if (PHASE1) {
                    v0 = fmaxf(v0, 0.f);
                    v1 = fmaxf(v1, 0.f);
                    __half2 hp;
                    hp.x = __float2half_rn(v0);
                    hp.y = __float2half_rn(v1);
                    size_t bo = (size_t)slot * H_DIM + n0 + cl;
                    *(__half2*)&g_h[bo] = hp;
                } else {
                    size_t bo = (size_t)(slot >> 1) * D_DIM + n0 + cl;
                    red_add_f32(&yout[bo],     gp * v0);
                    red_add_f32(&yout[bo + 1], gp * v1);
                }
            }
        }
    }
}

// ---------------- aux ----------------
__global__ void aux_kernel(float* __restrict__ y, long long out_size) {
    if (threadIdx.x == 0) {
        float aux = 0.f;
        const float invBT = 1.f / (float)BT;
#pragma unroll
        for (int e = 0; e < E_NUM; e++)
            aux += (g_imp[e] * invBT) * ((float)g_loadc[e] * invBT);
        aux *= (float)E_NUM * 0.01f;
        y[out_size - 1] = aux;
    }
}

// ---------------- launch ----------------
extern "C" void kernel_launch(void* const* d_in, const int* in_sizes, int n_in,
                              void* d_out, int out_size) {
    const float* x  = (const float*)d_in[0];
    const float* gW = (const float*)d_in[1];
    const float* w1 = (const float*)d_in[2];
    const float* b1 = (const float*)d_in[3];
    const float* w2 = (const float*)d_in[4];
    const float* b2 = (const float*)d_in[5];
    float* out = (float*)d_out;

    const int SMEM_BYTES = 3 * 49152;   // 144 KB dynamic
    cudaFuncSetAttribute(gemm_tc<H_DIM, D_DIM, true>,
                         cudaFuncAttributeMaxDynamicSharedMemorySize, SMEM_BYTES);
    cudaFuncSetAttribute(gemm_tc<D_DIM, H_DIM, false>,
                         cudaFuncAttributeMaxDynamicSharedMemorySize, SMEM_BYTES);

    init_kernel<<<1, 32>>>();
    zero_y_kernel<<<(BT * D_DIM / 4) / 256, 256>>>(out);
    router_kernel<<<BT / 8, 256>>>(x, gW);
    convert_w_kernel<D_DIM, H_DIM, true ><<<dim3(H_DIM / 32, D_DIM / 32, E_NUM), 256>>>(w1);
    convert_w_kernel<H_DIM, D_DIM, false><<<dim3(D_DIM / 32, H_DIM / 32, E_NUM), 256>>>(w2);

    gemm_tc<H_DIM, D_DIM, true ><<<dim3(H_DIM / 256, CAP / 128, E_NUM), 512, SMEM_BYTES>>>(b1, out);
    gemm_tc<D_DIM, H_DIM, false><<<dim3(D_DIM / 256, CAP / 128, E_NUM), 512, SMEM_BYTES>>>(b2, out);

    aux_kernel<<<1, 32>>>(out, (long long)out_size);
}

// round 11
// speedup vs baseline: 1.4837x; 1.4837x over previous
#include <cuda_runtime.h>
#include <cuda_fp16.h>
#include <math.h>
#include <stdint.h>

#define BT      8192
#define D_DIM   1024
#define E_NUM   8
#define H_DIM   4096
#define CAP     (2*BT)
#define NSLOT   (2*BT)

// ---------------- device scratch ----------------
__device__ __half g_x[(size_t)BT * D_DIM];
__device__ __half g_w1t[(size_t)E_NUM * H_DIM * D_DIM];
__device__ __half g_w2t[(size_t)E_NUM * D_DIM * H_DIM];
__device__ __half g_h[(size_t)NSLOT * H_DIM];
__device__ int   g_slots[E_NUM * CAP];
__device__ float g_gp[NSLOT];
__device__ int   g_cnt[E_NUM];
__device__ float g_imp[E_NUM];
__device__ int   g_loadc[E_NUM];

// ---------------- PTX helpers ----------------
__device__ __forceinline__ uint32_t smem_u32(const void* p) {
    return (uint32_t)__cvta_generic_to_shared(p);
}
__device__ __forceinline__ void cp_async16(uint32_t dst, const void* src) {
    asm volatile("cp.async.cg.shared.global [%0], [%1], 16;" :: "r"(dst), "l"(src));
}
#define CP_COMMIT() asm volatile("cp.async.commit_group;" ::: "memory")
#define CP_WAIT1()  asm volatile("cp.async.wait_group 1;" ::: "memory")

__device__ __forceinline__ void ldmatrix_x4(uint32_t* r, uint32_t addr) {
    asm volatile("ldmatrix.sync.aligned.m8n8.x4.shared.b16 {%0,%1,%2,%3}, [%4];"
        : "=r"(r[0]), "=r"(r[1]), "=r"(r[2]), "=r"(r[3]) : "r"(addr));
}
__device__ __forceinline__ void mma_16816(float* d, const uint32_t* a,
                                          uint32_t b0, uint32_t b1) {
    asm volatile(
        "mma.sync.aligned.m16n8k16.row.col.f32.f16.f16.f32 "
        "{%0,%1,%2,%3}, {%4,%5,%6,%7}, {%8,%9}, {%0,%1,%2,%3};"
        : "+f"(d[0]), "+f"(d[1]), "+f"(d[2]), "+f"(d[3])
        : "r"(a[0]), "r"(a[1]), "r"(a[2]), "r"(a[3]), "r"(b0), "r"(b1));
}
__device__ __forceinline__ void red_add_f32(float* addr, float v) {
    asm volatile("red.global.add.f32 [%0], %1;" :: "l"(addr), "f"(v) : "memory");
}

// ---------------- init ----------------
__global__ void init_kernel() {
    int i = threadIdx.x;
    if (i < E_NUM) { g_cnt[i] = 0; g_imp[i] = 0.f; g_loadc[i] = 0; }
}

// ---------------- zero y ----------------
__global__ void __launch_bounds__(256) zero_y_kernel(float* __restrict__ y) {
    size_t i = (size_t)blockIdx.x * 256 + threadIdx.x;
    ((float4*)y)[i] = make_float4(0.f, 0.f, 0.f, 0.f);
}

// ---------------- router (+ fused x->fp16 conversion) ----------------
__global__ void __launch_bounds__(256) router_kernel(const float* __restrict__ x,
                                                     const float* __restrict__ gW) {
    __shared__ float sW[E_NUM][D_DIM];
    __shared__ float s_imp[E_NUM];
    __shared__ int   s_load[E_NUM];
    int tid = threadIdx.x;
    if (tid < E_NUM) { s_imp[tid] = 0.f; s_load[tid] = 0; }
    for (int i = tid; i < D_DIM * E_NUM; i += 256) {
        int d = i / E_NUM, e = i % E_NUM;
        sW[e][d] = gW[i];
    }
    __syncthreads();

    int warp = tid >> 5, lane = tid & 31;
    int t = blockIdx.x * 8 + warp;
    const float* xr = x + (size_t)t * D_DIM;

    float acc[E_NUM];
#pragma unroll
    for (int e = 0; e < E_NUM; e++) acc[e] = 0.f;
    for (int d4 = lane; d4 < D_DIM / 4; d4 += 32) {
        float4 v = ((const float4*)xr)[d4];
        float f[4] = {v.x, v.y, v.z, v.w};
        __half h[4];
#pragma unroll
        for (int q = 0; q < 4; q++) {
            h[q] = __float2half_rn(f[q]);
#pragma unroll
            for (int e = 0; e < E_NUM; e++)
                acc[e] = fmaf(f[q], sW[e][d4 * 4 + q], acc[e]);
        }
        ((uint2*)g_x)[(size_t)t * (D_DIM / 4) + d4] = *(uint2*)&h[0];
    }
#pragma unroll
    for (int off = 16; off > 0; off >>= 1) {
#pragma unroll
        for (int e = 0; e < E_NUM; e++)
            acc[e] += __shfl_xor_sync(0xffffffffu, acc[e], off);
    }

    if (lane == 0) {
        float mx = acc[0];
#pragma unroll
        for (int e = 1; e < E_NUM; e++) mx = fmaxf(mx, acc[e]);
        float p[E_NUM], s = 0.f;
#pragma unroll
        for (int e = 0; e < E_NUM; e++) { p[e] = expf(acc[e] - mx); s += p[e]; }
        float inv = 1.f / s;
#pragma unroll
        for (int e = 0; e < E_NUM; e++) p[e] *= inv;

        int e1 = 0; float v1 = p[0];
#pragma unroll
        for (int e = 1; e < E_NUM; e++) if (p[e] > v1) { v1 = p[e]; e1 = e; }
        int e2 = -1; float v2 = -1.f;
#pragma unroll
        for (int e = 0; e < E_NUM; e++) if (e != e1 && p[e] > v2) { v2 = p[e]; e2 = e; }

        float ginv = 1.f / (v1 + v2);
        g_gp[2 * t]     = v1 * ginv;
        g_gp[2 * t + 1] = v2 * ginv;

        int p1 = atomicAdd(&g_cnt[e1], 1); g_slots[e1 * CAP + p1] = 2 * t;
        int p2 = atomicAdd(&g_cnt[e2], 1); g_slots[e2 * CAP + p2] = 2 * t + 1;
#pragma unroll
        for (int e = 0; e < E_NUM; e++) atomicAdd(&s_imp[e], p[e]);
        atomicAdd(&s_load[e1], 1);
    }
    __syncthreads();
    if (tid < E_NUM) {
        atomicAdd(&g_imp[tid], s_imp[tid]);
        atomicAdd(&g_loadc[tid], s_load[tid]);
    }
}

// ---------------- convert + transpose weights (single fp16) ----------------
template <int K, int N, bool IS_W1>
__global__ void __launch_bounds__(256) convert_w_kernel(const float* __restrict__ W) {
    __shared__ float tile[32][33];
    int e  = blockIdx.z;
    int n0 = blockIdx.x * 32;
    int k0 = blockIdx.y * 32;
    int t  = threadIdx.x;
    const float* Wb = W + (size_t)e * K * N;
#pragma unroll
    for (int j = 0; j < 4; j++) {
        int i = t + 256 * j;
        int k = i >> 5, n = i & 31;
        tile[k][n] = Wb[(size_t)(k0 + k) * N + n0 + n];
    }
    __syncthreads();
    __half* th = (IS_W1 ? g_w1t : g_w2t) + (size_t)e * N * K;
    int nn = t >> 3;
    int kc = (t & 7) * 4;
    __half h[4];
#pragma unroll
    for (int q = 0; q < 4; q++) h[q] = __float2half_rn(tile[kc + q][nn]);
    size_t o = (size_t)(n0 + nn) * K + k0 + kc;
    *(uint2*)&th[o] = *(uint2*)&h[0];
}

// ---------------- mma.sync grouped GEMM ----------------
// CTA tile 128x256, 256 threads (8 warps 2m x 4n; warp tile 64x64).
// K-chunk 64, 3-stage cp.async (144KB), single sync per chunk.
// Register double-buffered fragments hide ldmatrix latency at 2 warps/SMSP.
// PHASE2 fuses gate-weighted reduce into y via red.global.
template <int N_TOT, int K_SIZE, bool PHASE1>
__global__ void __launch_bounds__(256, 1) gemm_tc(const float* __restrict__ bias,
                                                  float* __restrict__ yout) {
    int e   = blockIdx.z;
    int cnt = g_cnt[e];
    int m0  = blockIdx.y * 128;
    if (m0 >= cnt) return;
    int n0  = blockIdx.x * 256;

    extern __shared__ char smem[];
    uint32_t sb = smem_u32(smem);
    const int STAGE = 49152;            // 16KB A + 32KB B
    const int AOF = 0, BOF = 16384;

    __shared__ int   sSlot[128];
    __shared__ float sBias[256];
    __shared__ float sGp[128];

    int tid  = threadIdx.x;
    int lane = tid & 31;
    int w    = tid >> 5;       // 0..7
    int wm   = w >> 2;         // 0..1, 64-row slab
    int wn   = w & 3;          // 0..3, 64-col slab

    if (tid < 128) {
        int m = m0 + tid;
        int s = (m < cnt) ? g_slots[e * CAP + m] : -1;
        sSlot[tid] = s;
        if (!PHASE1) sGp[tid] = (s >= 0) ? g_gp[s] : 0.f;
    }
    sBias[tid] = bias[(size_t)e * N_TOT + n0 + tid];
    __syncthreads();

    // zero A areas of all stages if ragged m-tile
    if (cnt - m0 < 128) {
#pragma unroll
        for (int s = 0; s < 3; s++) {
            uint32_t base = sb + s * STAGE + AOF;
            for (int off = tid * 16; off < 16384; off += 256 * 16)
                asm volatile("st.shared.v4.b32 [%0], {%1,%1,%1,%1};" :: "r"(base + off), "r"(0) : "memory");
        }
        __syncthreads();
    }

    const __half* Ap = PHASE1 ? g_x   : g_h;
    const __half* Bp = PHASE1 ? g_w1t : g_w2t;

    const char* aP[4];
    const char* bP[8];
    bool aval[4];
    uint32_t dswA[4], dswB[8];
    int colB = (tid & 7) * 16;
#pragma unroll
    for (int j = 0; j < 4; j++) {
        int row = (tid >> 3) + j * 32;
        int s   = sSlot[row];
        aval[j] = (s >= 0);
        size_t arow = 0;
        if (aval[j]) arow = PHASE1 ? (size_t)(s >> 1) : (size_t)s;
        aP[j] = (const char*)(Ap + arow * K_SIZE) + colB;
        uint32_t off = (uint32_t)row * 128 + colB;
        dswA[j] = off ^ ((off >> 3) & 0x70);
    }
#pragma unroll
    for (int j = 0; j < 8; j++) {
        int row = (tid >> 3) + j * 32;      // 0..255
        size_t nrow = (size_t)e * N_TOT + n0 + row;
        bP[j] = (const char*)(Bp + nrow * K_SIZE) + colB;
        uint32_t off = (uint32_t)row * 128 + colB;
        dswB[j] = off ^ ((off >> 3) & 0x70);
    }

#define LOAD_CHUNK(c) do { \
        uint32_t base_ = sb + ((c) % 3) * STAGE; \
        size_t kb_ = (size_t)(c) * 128; \
        _Pragma("unroll") \
        for (int j = 0; j < 4; j++) \
            if (aval[j]) cp_async16(base_ + AOF + dswA[j], aP[j] + kb_); \
        _Pragma("unroll") \
        for (int j = 0; j < 8; j++) \
            cp_async16(base_ + BOF + dswB[j], bP[j] + kb_); \
    } while (0)

    int lrow = ((lane >> 3) & 1) * 8 + (lane & 7);
    int lkb  = (lane >> 4) * 16;

    // fragment load for one k16 step into the given buffers
#define LDFRAG(kk, AH, BH) do { \
        int kb_f = (kk) * 32 + lkb; \
        _Pragma("unroll") \
        for (int mi = 0; mi < 4; mi++) { \
            uint32_t off = (uint32_t)(wm * 64 + mi * 16 + lrow) * 128 + kb_f; \
            uint32_t sw  = off ^ ((off >> 3) & 0x70); \
            ldmatrix_x4((AH)[mi], base + AOF + sw); \
        } \
        _Pragma("unroll") \
        for (int ng = 0; ng < 4; ng++) { \
            uint32_t off = (uint32_t)(wn * 64 + ng * 16 + lrow) * 128 + kb_f; \
            uint32_t sw  = off ^ ((off >> 3) & 0x70); \
            ldmatrix_x4((BH)[ng], base + BOF + sw); \
        } \
    } while (0)

    float acc[4][8][4];
#pragma unroll
    for (int i = 0; i < 4; i++)
#pragma unroll
        for (int j = 0; j < 8; j++)
#pragma unroll
            for (int q = 0; q < 4; q++) acc[i][j][q] = 0.f;

    constexpr int C = K_SIZE / 64;
    LOAD_CHUNK(0); CP_COMMIT();
    LOAD_CHUNK(1); CP_COMMIT();

    uint32_t ah2[2][4][4], bh2[2][4][4];

    for (int c = 0; c < C; c++) {
        uint32_t base = sb + (c % 3) * STAGE;
        CP_WAIT1();
        __syncthreads();
        // prefetch chunk c+2 into stage (c-1)%3 — drained, proven by barrier above
        if (c + 2 < C) LOAD_CHUNK(c + 2);
        CP_COMMIT();

        LDFRAG(0, ah2[0], bh2[0]);
#pragma unroll
        for (int kk = 0; kk < 4; kk++) {
            int cur = kk & 1;
            if (kk < 3) LDFRAG(kk + 1, ah2[cur ^ 1], bh2[cur ^ 1]);
#pragma unroll
            for (int mi = 0; mi < 4; mi++) {
#pragma unroll
                for (int ng = 0; ng < 4; ng++) {
#pragma unroll
                    for (int jj = 0; jj < 2; jj++) {
                        int nj = ng * 2 + jj;
                        mma_16816(acc[mi][nj], ah2[cur][mi],
                                  bh2[cur][ng][jj], bh2[cur][ng][jj + 2]);
                    }
                }
            }
        }
    }
#undef LOAD_CHUNK
#undef LDFRAG

    // ---------------- epilogue ----------------
#pragma unroll
    for (int mi = 0; mi < 4; mi++) {
#pragma unroll
        for (int h2 = 0; h2 < 2; h2++) {
            int rloc = wm * 64 + mi * 16 + h2 * 8 + (lane >> 2);
            int slot = sSlot[rloc];
            if (slot < 0) continue;
            float gp = PHASE1 ? 0.f : sGp[rloc];
#pragma unroll
            for (int nj = 0; nj < 8; nj++) {
                int cl = wn * 64 + nj * 8 + (lane & 3) * 2;
                float v0 = acc[mi][nj][h2 * 2 + 0] + sBias[cl];
                float v1 = acc[mi][nj][h2 * 2 + 1] + sBias[cl + 1];
                if (PHASE1) {
                    v0 = fmaxf(v0, 0.f);
                    v1 = fmaxf(v1, 0.f);
                    __half2 hp;
                    hp.x = __float2half_rn(v0);
                    hp.y = __float2half_rn(v1);
                    size_t bo = (size_t)slot * H_DIM + n0 + cl;
                    *(__half2*)&g_h[bo] = hp;
                } else {
                    size_t bo = (size_t)(slot >> 1) * D_DIM + n0 + cl;
                    red_add_f32(&yout[bo],     gp * v0);
                    red_add_f32(&yout[bo + 1], gp * v1);
                }
            }
        }
    }
}

// ---------------- aux ----------------
__global__ void aux_kernel(float* __restrict__ y, long long out_size) {
    if (threadIdx.x == 0) {
        float aux = 0.f;
        const float invBT = 1.f / (float)BT;
#pragma unroll
        for (int e = 0; e < E_NUM; e++)
            aux += (g_imp[e] * invBT) * ((float)g_loadc[e] * invBT);
        aux *= (float)E_NUM * 0.01f;
        y[out_size - 1] = aux;
    }
}

// ---------------- launch ----------------
extern "C" void kernel_launch(void* const* d_in, const int* in_sizes, int n_in,
                              void* d_out, int out_size) {
    const float* x  = (const float*)d_in[0];
    const float* gW = (const float*)d_in[1];
    const float* w1 = (const float*)d_in[2];
    const float* b1 = (const float*)d_in[3];
    const float* w2 = (const float*)d_in[4];
    const float* b2 = (const float*)d_in[5];
    float* out = (float*)d_out;

    const int SMEM_BYTES = 3 * 49152;   // 144 KB dynamic
    cudaFuncSetAttribute(gemm_tc<H_DIM, D_DIM, true>,
                         cudaFuncAttributeMaxDynamicSharedMemorySize, SMEM_BYTES);
    cudaFuncSetAttribute(gemm_tc<D_DIM, H_DIM, false>,
                         cudaFuncAttributeMaxDynamicSharedMemorySize, SMEM_BYTES);

    init_kernel<<<1, 32>>>();
    zero_y_kernel<<<(BT * D_DIM / 4) / 256, 256>>>(out);
    router_kernel<<<BT / 8, 256>>>(x, gW);
    convert_w_kernel<D_DIM, H_DIM, true ><<<dim3(H_DIM / 32, D_DIM / 32, E_NUM), 256>>>(w1);
    convert_w_kernel<H_DIM, D_DIM, false><<<dim3(D_DIM / 32, H_DIM / 32, E_NUM), 256>>>(w2);

    gemm_tc<H_DIM, D_DIM, true ><<<dim3(H_DIM / 256, CAP / 128, E_NUM), 256, SMEM_BYTES>>>(b1, out);
    gemm_tc<D_DIM, H_DIM, false><<<dim3(D_DIM / 256, CAP / 128, E_NUM), 256, SMEM_BYTES>>>(b2, out);

    aux_kernel<<<1, 32>>>(out, (long long)out_size);
}

// round 12
// speedup vs baseline: 1.6996x; 1.1455x over previous
#include <cuda_runtime.h>
#include <cuda_fp16.h>
#include <math.h>
#include <stdint.h>

#define BT      8192
#define D_DIM   1024
#define E_NUM   8
#define H_DIM   4096
#define CAP     (2*BT)
#define NSLOT   (2*BT)

// ---------------- device scratch ----------------
__device__ __half g_x[(size_t)BT * D_DIM];
__device__ __half g_w1t[(size_t)E_NUM * H_DIM * D_DIM];
__device__ __half g_w2t[(size_t)E_NUM * D_DIM * H_DIM];
__device__ __half g_h[(size_t)NSLOT * H_DIM];
__device__ int   g_slots[E_NUM * CAP];
__device__ float g_gp[NSLOT];
__device__ int   g_cnt[E_NUM];
__device__ float g_imp[E_NUM];
__device__ int   g_loadc[E_NUM];

// ---------------- PTX helpers ----------------
__device__ __forceinline__ uint32_t smem_u32(const void* p) {
    return (uint32_t)__cvta_generic_to_shared(p);
}
__device__ __forceinline__ void cp_async16(uint32_t dst, const void* src) {
    asm volatile("cp.async.cg.shared.global [%0], [%1], 16;" :: "r"(dst), "l"(src));
}
#define CP_COMMIT() asm volatile("cp.async.commit_group;" ::: "memory")
#define CP_WAIT1()  asm volatile("cp.async.wait_group 1;" ::: "memory")

__device__ __forceinline__ void ldmatrix_x4(uint32_t* r, uint32_t addr) {
    asm volatile("ldmatrix.sync.aligned.m8n8.x4.shared.b16 {%0,%1,%2,%3}, [%4];"
        : "=r"(r[0]), "=r"(r[1]), "=r"(r[2]), "=r"(r[3]) : "r"(addr));
}
__device__ __forceinline__ void mma_16816(float* d, const uint32_t* a,
                                          uint32_t b0, uint32_t b1) {
    asm volatile(
        "mma.sync.aligned.m16n8k16.row.col.f32.f16.f16.f32 "
        "{%0,%1,%2,%3}, {%4,%5,%6,%7}, {%8,%9}, {%0,%1,%2,%3};"
        : "+f"(d[0]), "+f"(d[1]), "+f"(d[2]), "+f"(d[3])
        : "r"(a[0]), "r"(a[1]), "r"(a[2]), "r"(a[3]), "r"(b0), "r"(b1));
}
__device__ __forceinline__ void red_add_f32(float* addr, float v) {
    asm volatile("red.global.add.f32 [%0], %1;" :: "l"(addr), "f"(v) : "memory");
}

// ---------------- init ----------------
__global__ void init_kernel() {
    int i = threadIdx.x;
    if (i < E_NUM) { g_cnt[i] = 0; g_imp[i] = 0.f; g_loadc[i] = 0; }
}

// ---------------- zero y ----------------
__global__ void __launch_bounds__(256) zero_y_kernel(float* __restrict__ y) {
    size_t i = (size_t)blockIdx.x * 256 + threadIdx.x;
    ((float4*)y)[i] = make_float4(0.f, 0.f, 0.f, 0.f);
}

// ---------------- router (+ fused x->fp16 conversion) ----------------
__global__ void __launch_bounds__(256) router_kernel(const float* __restrict__ x,
                                                     const float* __restrict__ gW) {
    __shared__ float sW[E_NUM][D_DIM];
    __shared__ float s_imp[E_NUM];
    __shared__ int   s_load[E_NUM];
    int tid = threadIdx.x;
    if (tid < E_NUM) { s_imp[tid] = 0.f; s_load[tid] = 0; }
    for (int i = tid; i < D_DIM * E_NUM; i += 256) {
        int d = i / E_NUM, e = i % E_NUM;
        sW[e][d] = gW[i];
    }
    __syncthreads();

    int warp = tid >> 5, lane = tid & 31;
    int t = blockIdx.x * 8 + warp;
    const float* xr = x + (size_t)t * D_DIM;

    float acc[E_NUM];
#pragma unroll
    for (int e = 0; e < E_NUM; e++) acc[e] = 0.f;
    for (int d4 = lane; d4 < D_DIM / 4; d4 += 32) {
        float4 v = ((const float4*)xr)[d4];
        float f[4] = {v.x, v.y, v.z, v.w};
        __half h[4];
#pragma unroll
        for (int q = 0; q < 4; q++) {
            h[q] = __float2half_rn(f[q]);
#pragma unroll
            for (int e = 0; e < E_NUM; e++)
                acc[e] = fmaf(f[q], sW[e][d4 * 4 + q], acc[e]);
        }
        ((uint2*)g_x)[(size_t)t * (D_DIM / 4) + d4] = *(uint2*)&h[0];
    }
#pragma unroll
    for (int off = 16; off > 0; off >>= 1) {
#pragma unroll
        for (int e = 0; e < E_NUM; e++)
            acc[e] += __shfl_xor_sync(0xffffffffu, acc[e], off);
    }

    if (lane == 0) {
        float mx = acc[0];
#pragma unroll
        for (int e = 1; e < E_NUM; e++) mx = fmaxf(mx, acc[e]);
        float p[E_NUM], s = 0.f;
#pragma unroll
        for (int e = 0; e < E_NUM; e++) { p[e] = expf(acc[e] - mx); s += p[e]; }
        float inv = 1.f / s;
#pragma unroll
        for (int e = 0; e < E_NUM; e++) p[e] *= inv;

        int e1 = 0; float v1 = p[0];
#pragma unroll
        for (int e = 1; e < E_NUM; e++) if (p[e] > v1) { v1 = p[e]; e1 = e; }
        int e2 = -1; float v2 = -1.f;
#pragma unroll
        for (int e = 0; e < E_NUM; e++) if (e != e1 && p[e] > v2) { v2 = p[e]; e2 = e; }

        float ginv = 1.f / (v1 + v2);
        g_gp[2 * t]     = v1 * ginv;
        g_gp[2 * t + 1] = v2 * ginv;

        int p1 = atomicAdd(&g_cnt[e1], 1); g_slots[e1 * CAP + p1] = 2 * t;
        int p2 = atomicAdd(&g_cnt[e2], 1); g_slots[e2 * CAP + p2] = 2 * t + 1;
#pragma unroll
        for (int e = 0; e < E_NUM; e++) atomicAdd(&s_imp[e], p[e]);
        atomicAdd(&s_load[e1], 1);
    }
    __syncthreads();
    if (tid < E_NUM) {
        atomicAdd(&g_imp[tid], s_imp[tid]);
        atomicAdd(&g_loadc[tid], s_load[tid]);
    }
}

// ---------------- convert + transpose weights (single fp16, 16B stores) ----------------
// W: (E, K, N) fp32 -> Wt: (E, N, K) fp16. Tile: 64 k x 32 n per CTA.
template <int K, int N, bool IS_W1>
__global__ void __launch_bounds__(256) convert_w_kernel(const float* __restrict__ W) {
    __shared__ float tile[64][33];
    int e  = blockIdx.z;
    int n0 = blockIdx.x * 32;
    int k0 = blockIdx.y * 64;
    int t  = threadIdx.x;
    const float* Wb = W + (size_t)e * K * N;
#pragma unroll
    for (int j = 0; j < 8; j++) {
        int i = t + 256 * j;            // 0..2047
        int k = i >> 5, n = i & 31;
        tile[k][n] = Wb[(size_t)(k0 + k) * N + n0 + n];
    }
    __syncthreads();
    __half* th = (IS_W1 ? g_w1t : g_w2t) + (size_t)e * N * K;
    int nn = t >> 3;                    // 0..31
    int kc = (t & 7) * 8;               // 0..56
    __half h[8];
#pragma unroll
    for (int q = 0; q < 8; q++) h[q] = __float2half_rn(tile[kc + q][nn]);
    size_t o = (size_t)(n0 + nn) * K + k0 + kc;
    *(uint4*)&th[o] = *(uint4*)&h[0];
}

// ---------------- mma.sync grouped GEMM ----------------
// CTA tile 128x128, K-chunk 64, 3-stage cp.async (96KB), 2 CTAs/SM.
// Single __syncthreads per chunk. PHASE2 fuses gate-weighted reduce into y.
template <int N_TOT, int K_SIZE, bool PHASE1>
__global__ void __launch_bounds__(256, 2) gemm_tc(const float* __restrict__ bias,
                                                  float* __restrict__ yout) {
    int e   = blockIdx.z;
    int cnt = g_cnt[e];
    int m0  = blockIdx.y * 128;
    if (m0 >= cnt) return;
    int n0  = blockIdx.x * 128;

    extern __shared__ char smem[];
    uint32_t sb = smem_u32(smem);
    const int STAGE = 32768;
    const int AOF = 0, BOF = 16384;

    __shared__ int   sSlot[128];
    __shared__ float sBias[128];
    __shared__ float sGp[128];

    int tid  = threadIdx.x;
    int lane = tid & 31;
    int w    = tid >> 5;
    int wm   = w >> 2;
    int wn   = w & 3;

    if (tid < 128) {
        int m = m0 + tid;
        int s = (m < cnt) ? g_slots[e * CAP + m] : -1;
        sSlot[tid] = s;
        sBias[tid] = bias[(size_t)e * N_TOT + n0 + tid];
        if (!PHASE1) sGp[tid] = (s >= 0) ? g_gp[s] : 0.f;
    }
    __syncthreads();

    // zero A areas of all stages if ragged m-tile
    if (cnt - m0 < 128) {
#pragma unroll
        for (int s = 0; s < 3; s++) {
            uint32_t base = sb + s * STAGE + AOF;
            for (int off = tid * 16; off < 16384; off += 256 * 16)
                asm volatile("st.shared.v4.b32 [%0], {%1,%1,%1,%1};" :: "r"(base + off), "r"(0) : "memory");
        }
        __syncthreads();
    }

    const __half* Ap = PHASE1 ? g_x   : g_h;
    const __half* Bp = PHASE1 ? g_w1t : g_w2t;

    const char* aP[4];
    const char* bP[4];
    bool aval[4];
    uint32_t dsw[4];
    int colB = (tid & 7) * 16;
#pragma unroll
    for (int j = 0; j < 4; j++) {
        int row = (tid >> 3) + j * 32;
        int s   = sSlot[row];
        aval[j] = (s >= 0);
        size_t arow = 0;
        if (aval[j]) arow = PHASE1 ? (size_t)(s >> 1) : (size_t)s;
        aP[j] = (const char*)(Ap + arow * K_SIZE) + colB;
        size_t nrow = (size_t)e * N_TOT + n0 + row;
        bP[j] = (const char*)(Bp + nrow * K_SIZE) + colB;
        uint32_t off = (uint32_t)row * 128 + colB;
        dsw[j] = off ^ ((off >> 3) & 0x70);
    }

#define LOAD_CHUNK(c) do { \
        uint32_t base_ = sb + ((c) % 3) * STAGE; \
        size_t kb_ = (size_t)(c) * 128; \
        _Pragma("unroll") \
        for (int j = 0; j < 4; j++) { \
            if (aval[j]) cp_async16(base_ + AOF + dsw[j], aP[j] + kb_); \
            cp_async16(base_ + BOF + dsw[j], bP[j] + kb_); \
        } \
    } while (0)

    int lrow = ((lane >> 3) & 1) * 8 + (lane & 7);
    int lkb  = (lane >> 4) * 16;

    float acc[4][4][4];
#pragma unroll
    for (int i = 0; i < 4; i++)
#pragma unroll
        for (int j = 0; j < 4; j++)
#pragma unroll
            for (int q = 0; q < 4; q++) acc[i][j][q] = 0.f;

    constexpr int C = K_SIZE / 64;
    LOAD_CHUNK(0); CP_COMMIT();
    LOAD_CHUNK(1); CP_COMMIT();

    for (int c = 0; c < C; c++) {
        uint32_t base = sb + (c % 3) * STAGE;
        CP_WAIT1();
        __syncthreads();
        // prefetch chunk c+2 into stage (c-1)%3 — drained, proven by barrier above
        if (c + 2 < C) LOAD_CHUNK(c + 2);
        CP_COMMIT();

#pragma unroll
        for (int kk = 0; kk < 4; kk++) {
            int kb = kk * 32 + lkb;
            uint32_t ah[4][4];
#pragma unroll
            for (int mi = 0; mi < 4; mi++) {
                uint32_t off = (uint32_t)(wm * 64 + mi * 16 + lrow) * 128 + kb;
                uint32_t sw  = off ^ ((off >> 3) & 0x70);
                ldmatrix_x4(ah[mi], base + AOF + sw);
            }
            uint32_t bh[2][4];
#pragma unroll
            for (int ng = 0; ng < 2; ng++) {
                uint32_t off = (uint32_t)(wn * 32 + ng * 16 + lrow) * 128 + kb;
                uint32_t sw  = off ^ ((off >> 3) & 0x70);
                ldmatrix_x4(bh[ng], base + BOF + sw);
            }
#pragma unroll
            for (int mi = 0; mi < 4; mi++) {
#pragma unroll
                for (int ng = 0; ng < 2; ng++) {
#pragma unroll
                    for (int jj = 0; jj < 2; jj++) {
                        int nj = ng * 2 + jj;
                        mma_16816(acc[mi][nj], ah[mi], bh[ng][jj], bh[ng][jj + 2]);
                    }
                }
            }
        }
    }
#undef LOAD_CHUNK

    // ---------------- epilogue ----------------
#pragma unroll
    for (int mi = 0; mi < 4; mi++) {
#pragma unroll
        for (int h2 = 0; h2 < 2; h2++) {
            int rloc = wm * 64 + mi * 16 + h2 * 8 + (lane >> 2);
            int slot = sSlot[rloc];
            if (slot < 0) continue;
            float gp = PHASE1 ? 0.f : sGp[rloc];
#pragma unroll
            for (int nj = 0; nj < 4; nj++) {
                int cl = wn * 32 + nj * 8 + (lane & 3) * 2;
                float v0 = acc[mi][nj][h2 * 2 + 0] + sBias[cl];
                float v1 = acc[mi][nj][h2 * 2 + 1] + sBias[cl + 1];
                if (PHASE1) {
                    v0 = fmaxf(v0, 0.f);
                    v1 = fmaxf(v1, 0.f);
                    __half2 hp;
                    hp.x = __float2half_rn(v0);
                    hp.y = __float2half_rn(v1);
                    size_t bo = (size_t)slot * H_DIM + n0 + cl;
                    *(__half2*)&g_h[bo] = hp;
                } else {
                    size_t bo = (size_t)(slot >> 1) * D_DIM + n0 + cl;
                    red_add_f32(&yout[bo],     gp * v0);
                    red_add_f32(&yout[bo + 1], gp * v1);
                }
            }
        }
    }
}

// ---------------- aux ----------------
__global__ void aux_kernel(float* __restrict__ y, long long out_size) {
    if (threadIdx.x == 0) {
        float aux = 0.f;
        const float invBT = 1.f / (float)BT;
#pragma unroll
        for (int e = 0; e < E_NUM; e++)
            aux += (g_imp[e] * invBT) * ((float)g_loadc[e] * invBT);
        aux *= (float)E_NUM * 0.01f;
        y[out_size - 1] = aux;
    }
}

// ---------------- launch ----------------
extern "C" void kernel_launch(void* const* d_in, const int* in_sizes, int n_in,
                              void* d_out, int out_size) {
    const float* x  = (const float*)d_in[0];
    const float* gW = (const float*)d_in[1];
    const float* w1 = (const float*)d_in[2];
    const float* b1 = (const float*)d_in[3];
    const float* w2 = (const float*)d_in[4];
    const float* b2 = (const float*)d_in[5];
    float* out = (float*)d_out;

    const int SMEM_BYTES = 3 * 32768;   // 96 KB dynamic
    cudaFuncSetAttribute(gemm_tc<H_DIM, D_DIM, true>,
                         cudaFuncAttributeMaxDynamicSharedMemorySize, SMEM_BYTES);
    cudaFuncSetAttribute(gemm_tc<D_DIM, H_DIM, false>,
                         cudaFuncAttributeMaxDynamicSharedMemorySize, SMEM_BYTES);

    init_kernel<<<1, 32>>>();
    zero_y_kernel<<<(BT * D_DIM / 4) / 256, 256>>>(out);
    router_kernel<<<BT / 8, 256>>>(x, gW);
    convert_w_kernel<D_DIM, H_DIM, true ><<<dim3(H_DIM / 32, D_DIM / 64, E_NUM), 256>>>(w1);
    convert_w_kernel<H_DIM, D_DIM, false><<<dim3(D_DIM / 32, H_DIM / 64, E_NUM), 256>>>(w2);

    gemm_tc<H_DIM, D_DIM, true ><<<dim3(H_DIM / 128, CAP / 128, E_NUM), 256, SMEM_BYTES>>>(b1, out);
    gemm_tc<D_DIM, H_DIM, false><<<dim3(D_DIM / 128, CAP / 128, E_NUM), 256, SMEM_BYTES>>>(b2, out);

    aux_kernel<<<1, 32>>>(out, (long long)out_size);
}